// round 1
// baseline (speedup 1.0000x reference)
#include <cuda_runtime.h>
#include <math_constants.h>

// DilateErode: tropical matmul.
//   dilated[b,n] = max_f ( xb[b,f] + D[f,n] )   (xb = x with appended 0 bias feature)
//   eroded [b,n] = min_f ( xb[b,f] - E[f,n] ) = -max_f( (-xb[b,f]) + E[f,n] )
// Unified as max-plus with sign-flipped x for the erosion half. Bit-exact vs fp32 ref.
//
// Shapes: x (1024,1024) f32, D/E (1025,256) f32, out (1024,512) f32 = [eroded | dilated].

#define Fdim 1024
#define Bdim 1024
#define NW   256      // weight cols per matrix
#define OUTC 512
#define BM   64
#define BN   64
#define KB   32

__global__ __launch_bounds__(256)
void trop_kernel(const float* __restrict__ x,
                 const float* __restrict__ dil,
                 const float* __restrict__ ero,
                 float* __restrict__ out)
{
    __shared__ float xs[KB][BM];   // k-major, XOR-swizzled columns
    __shared__ float ws[KB][BN];

    const int tid = threadIdx.x;
    const int tx  = tid & 15;          // col group (4 cols each)
    const int ty  = tid >> 4;          // row group (4 rows each)
    const int rowBase = blockIdx.y * BM;

    const bool erode   = (blockIdx.x < 4);
    const float sgn    = erode ? -1.0f : 1.0f;
    const float* W     = erode ? ero : dil;
    const int wColBase = (blockIdx.x & 3) * BN;
    const int outColBase = blockIdx.x * BN;

    float acc[4][4];
#pragma unroll
    for (int i = 0; i < 4; ++i)
#pragma unroll
        for (int j = 0; j < 4; ++j)
            acc[i][j] = -CUDART_INF_F;

    for (int k0 = 0; k0 < Fdim; k0 += KB) {
        // ---- load x tile (BM x KB), sign applied, transposed into xs[k][row^swz] ----
#pragma unroll
        for (int it = 0; it < 2; ++it) {
            int i   = tid + it * 256;       // 512 float4 total
            int row = i >> 3;               // 8 float4 per row of 32 k
            int kq  = i & 7;
            float4 v = *(const float4*)&x[(size_t)(rowBase + row) * Fdim + k0 + kq * 4];
            int col = row ^ (kq << 2);      // swizzle: kq == (kk>>2) for these 4 kk
            xs[kq * 4 + 0][col] = v.x * sgn;
            xs[kq * 4 + 1][col] = v.y * sgn;
            xs[kq * 4 + 2][col] = v.z * sgn;
            xs[kq * 4 + 3][col] = v.w * sgn;
        }
        // ---- load w tile (KB x BN) ----
#pragma unroll
        for (int it = 0; it < 2; ++it) {
            int i    = tid + it * 256;      // 512 float4 total
            int krow = i >> 4;              // 16 float4 per k-row
            int cq   = i & 15;
            *(float4*)&ws[krow][cq * 4] =
                *(const float4*)&W[(size_t)(k0 + krow) * NW + wColBase + cq * 4];
        }
        __syncthreads();

#pragma unroll
        for (int kk = 0; kk < KB; ++kk) {
            float4 xv = *(const float4*)&xs[kk][(ty * 4) ^ (((kk >> 2) & 7) << 2)];
            float4 wv = *(const float4*)&ws[kk][tx * 4];
            float xa[4] = {xv.x, xv.y, xv.z, xv.w};
            float wa[4] = {wv.x, wv.y, wv.z, wv.w};
#pragma unroll
            for (int i = 0; i < 4; ++i)
#pragma unroll
                for (int j = 0; j < 4; ++j)
                    acc[i][j] = fmaxf(acc[i][j], xa[i] + wa[j]);
        }
        __syncthreads();
    }

    // ---- bias feature f = 1024 (xb = 0): contributes W[1024, n] + 0 ----
    {
        float4 wb = *(const float4*)&W[(size_t)Fdim * NW + wColBase + tx * 4];
        float wa[4] = {wb.x, wb.y, wb.z, wb.w};
#pragma unroll
        for (int i = 0; i < 4; ++i)
#pragma unroll
            for (int j = 0; j < 4; ++j)
                acc[i][j] = fmaxf(acc[i][j], wa[j]);
    }

    // ---- store (negate back for erosion half) ----
#pragma unroll
    for (int i = 0; i < 4; ++i) {
        int row = rowBase + ty * 4 + i;
        float4 o;
        o.x = acc[i][0] * sgn;
        o.y = acc[i][1] * sgn;
        o.z = acc[i][2] * sgn;
        o.w = acc[i][3] * sgn;
        *(float4*)&out[(size_t)row * OUTC + outColBase + tx * 4] = o;
    }
}

extern "C" void kernel_launch(void* const* d_in, const int* in_sizes, int n_in,
                              void* d_out, int out_size)
{
    const float* x   = (const float*)d_in[0];   // (1024, 1024)
    const float* dil = (const float*)d_in[1];   // (1025, 256)
    const float* ero = (const float*)d_in[2];   // (1025, 256)
    float* out = (float*)d_out;                 // (1024, 512)

    dim3 grid(OUTC / BN, Bdim / BM);            // (8, 16) = 128 blocks
    trop_kernel<<<grid, 256>>>(x, dil, ero, out);
}

// round 2
// speedup vs baseline: 1.1571x; 1.1571x over previous
#include <cuda_runtime.h>
#include <math_constants.h>

// DilateErode tropical matmul, max-plus unified form:
//   dilated[b,n] = max_f ( xb[b,f] + D[f,n] )
//   eroded [b,n] = min_f ( xb[b,f] - E[f,n] ) = -max_f( (-xb[b,f]) + E[f,n] )
// Sign flips done via sign-bit XOR (bit-exact vs fp32 reference).
// Double-buffered smem pipeline, 1 barrier/tile, prefetch in registers.

#define Fdim 1024
#define Bdim 1024
#define NW   256
#define OUTC 512
#define BM   64
#define BN   64
#define KB   32
#define NT   (Fdim / KB)

__device__ __forceinline__ float flips(float v, unsigned m) {
    return __uint_as_float(__float_as_uint(v) ^ m);
}

__global__ __launch_bounds__(256, 1)
void trop_kernel(const float* __restrict__ x,
                 const float* __restrict__ dil,
                 const float* __restrict__ ero,
                 float* __restrict__ out)
{
    __shared__ float xs[2][KB][BM];   // k-major, XOR-swizzled columns
    __shared__ float ws[2][KB][BN];

    const int tid = threadIdx.x;
    const int tx  = tid & 15;          // 4 output cols each
    const int ty  = tid >> 4;          // 4 output rows each
    const int rowBase = blockIdx.y * BM;

    const bool erode     = (blockIdx.x < 4);
    const unsigned smask = erode ? 0x80000000u : 0u;
    const float* __restrict__ W = erode ? ero : dil;
    const int wColBase   = (blockIdx.x & 3) * BN;
    const int outColBase = blockIdx.x * BN;

    // x loader mapping: 512 float4 per tile, thread covers 2 (rows r, r+32)
    const int xrow  = tid >> 3;                  // 0..31
    const int xkq   = tid & 7;                   // which float4 along k
    const int xcol0 = xrow ^ (xkq << 2);         // swizzle (bits 2..4 only)
    const int xcol1 = (xrow + 32) ^ (xkq << 2);
    const float* xp = x + (size_t)(rowBase + xrow) * Fdim + (xkq << 2);

    // w loader mapping: 512 float4 per tile, thread covers k rows wk, wk+16
    const int wk  = tid >> 4;                    // 0..15
    const int wcq = tid & 15;
    const float* wp = W + (size_t)wk * NW + wColBase + (wcq << 2);

    // prefetch tile 0
    float4 xr0 = *(const float4*)xp;
    float4 xr1 = *(const float4*)(xp + 32 * Fdim);
    float4 wr0 = *(const float4*)wp;
    float4 wr1 = *(const float4*)(wp + 16 * NW);

    float acc[4][4];
#pragma unroll
    for (int i = 0; i < 4; ++i)
#pragma unroll
        for (int j = 0; j < 4; ++j)
            acc[i][j] = -CUDART_INF_F;

#pragma unroll 2
    for (int t = 0; t < NT; ++t) {
        const int buf = t & 1;
        float (*xsb)[BM] = xs[buf];
        float (*wsb)[BN] = ws[buf];

        // ---- store prefetched tile (x transposed + sign-flipped) ----
        xsb[xkq * 4 + 0][xcol0] = flips(xr0.x, smask);
        xsb[xkq * 4 + 1][xcol0] = flips(xr0.y, smask);
        xsb[xkq * 4 + 2][xcol0] = flips(xr0.z, smask);
        xsb[xkq * 4 + 3][xcol0] = flips(xr0.w, smask);
        xsb[xkq * 4 + 0][xcol1] = flips(xr1.x, smask);
        xsb[xkq * 4 + 1][xcol1] = flips(xr1.y, smask);
        xsb[xkq * 4 + 2][xcol1] = flips(xr1.z, smask);
        xsb[xkq * 4 + 3][xcol1] = flips(xr1.w, smask);
        *(float4*)&wsb[wk     ][wcq * 4] = wr0;
        *(float4*)&wsb[wk + 16][wcq * 4] = wr1;

        // ---- prefetch next tile (hidden under this tile's compute) ----
        if (t + 1 < NT) {
            xp += KB;
            wp += (size_t)KB * NW;
            xr0 = *(const float4*)xp;
            xr1 = *(const float4*)(xp + 32 * Fdim);
            wr0 = *(const float4*)wp;
            wr1 = *(const float4*)(wp + 16 * NW);
        }
        __syncthreads();   // single barrier per tile (double buffer)

        // ---- compute ----
#pragma unroll
        for (int kk = 0; kk < KB; ++kk) {
            float4 xv = *(const float4*)&xsb[kk][(ty * 4) ^ (kk & 28)];
            float4 wv = *(const float4*)&wsb[kk][tx * 4];
            float xa[4] = {xv.x, xv.y, xv.z, xv.w};
            float wa[4] = {wv.x, wv.y, wv.z, wv.w};
#pragma unroll
            for (int i = 0; i < 4; ++i)
#pragma unroll
                for (int j = 0; j < 4; ++j)
                    acc[i][j] = fmaxf(acc[i][j], xa[i] + wa[j]);
        }
    }

    // ---- bias feature f = 1024 (xb contribution is 0) ----
    {
        float4 wb = *(const float4*)&W[(size_t)Fdim * NW + wColBase + (tx << 2)];
        float wa[4] = {wb.x, wb.y, wb.z, wb.w};
#pragma unroll
        for (int i = 0; i < 4; ++i)
#pragma unroll
            for (int j = 0; j < 4; ++j)
                acc[i][j] = fmaxf(acc[i][j], wa[j]);
    }

    // ---- store, undoing the sign flip for the erosion half ----
#pragma unroll
    for (int i = 0; i < 4; ++i) {
        int row = rowBase + ty * 4 + i;
        float4 o;
        o.x = flips(acc[i][0], smask);
        o.y = flips(acc[i][1], smask);
        o.z = flips(acc[i][2], smask);
        o.w = flips(acc[i][3], smask);
        *(float4*)&out[(size_t)row * OUTC + outColBase + (tx << 2)] = o;
    }
}

extern "C" void kernel_launch(void* const* d_in, const int* in_sizes, int n_in,
                              void* d_out, int out_size)
{
    const float* x   = (const float*)d_in[0];   // (1024, 1024)
    const float* dil = (const float*)d_in[1];   // (1025, 256)
    const float* ero = (const float*)d_in[2];   // (1025, 256)
    float* out = (float*)d_out;                 // (1024, 512) = [eroded | dilated]

    dim3 grid(OUTC / BN, Bdim / BM);            // (8, 16) = 128 blocks, 1 wave
    trop_kernel<<<grid, 256>>>(x, dil, ero, out);
}